// round 3
// baseline (speedup 1.0000x reference)
#include <cuda_runtime.h>
#include <float.h>

// ChamferDist (adv->ori): loss = mean_b( w_b * mean_k( min_j ||adv[bk]-ori[bj]||^2 ) )
//
// min_j(a2 + b2_j - 2 a.b_j) = a2 + min_j(b2_j - 2 a.b_j).
// Ori points stored in smem as PAIRS for packed f32x2 FMA:
//   sXY[p] = (-2x0, -2x1, -2y0, -2y1)
//   sZW[p] = (-2z0, -2z1, ||o0||^2, ||o1||^2)
// Inner loop per 2 ori points: 2 LDS.128 + 3 FFMA2 + 2 FMNMX.
// 8 independent min accumulators kill the FMNMX serial chain.
// Single fused kernel: per-CTA partial -> atomic counter -> last CTA writes out.

#define CD_THREADS 256
#define CD_MAX_BLOCKS 4096

__device__ float        g_cd_partial[CD_MAX_BLOCKS];
__device__ unsigned int g_cd_count;

__device__ __forceinline__ unsigned long long pack_dup(float v) {
    unsigned long long r;
    asm("mov.b64 %0, {%1, %1};" : "=l"(r) : "f"(v));
    return r;
}

__device__ __forceinline__ unsigned long long fma2(unsigned long long a,
                                                   unsigned long long b,
                                                   unsigned long long c) {
    unsigned long long d;
    asm("fma.rn.f32x2 %0, %1, %2, %3;" : "=l"(d) : "l"(a), "l"(b), "l"(c));
    return d;
}

__device__ __forceinline__ void unpack2(unsigned long long v, float& lo, float& hi) {
    asm("mov.b64 {%0, %1}, %2;" : "=f"(lo), "=f"(hi) : "l"(v));
}

__global__ __launch_bounds__(CD_THREADS)
void chamfer_fused_kernel(const float* __restrict__ adv,
                          const float* __restrict__ ori,
                          const float* __restrict__ w,
                          float* __restrict__ out,
                          int K, int tilesPerBatch, float scale,
                          int nblocks) {
    extern __shared__ float smem_raw[];
    const int pairs = K >> 1;               // K assumed even (K=4096)
    float4* sXY = (float4*)smem_raw;        // pairs entries
    float4* sZW = ((float4*)smem_raw) + pairs;

    const int tile = blockIdx.x % tilesPerBatch;
    const int b    = blockIdx.x / tilesPerBatch;

    // Cooperative fill: transform ori points into packed pair layout.
    const float* __restrict__ orib = ori + (size_t)b * K * 3;
    for (int p = threadIdx.x; p < pairs; p += CD_THREADS) {
        const int j0 = 2 * p, j1 = 2 * p + 1;
        float x0 = orib[3 * j0 + 0], y0 = orib[3 * j0 + 1], z0 = orib[3 * j0 + 2];
        float x1 = orib[3 * j1 + 0], y1 = orib[3 * j1 + 1], z1 = orib[3 * j1 + 2];
        sXY[p] = make_float4(-2.0f * x0, -2.0f * x1, -2.0f * y0, -2.0f * y1);
        sZW[p] = make_float4(-2.0f * z0, -2.0f * z1,
                             x0 * x0 + y0 * y0 + z0 * z0,
                             x1 * x1 + y1 * y1 + z1 * z1);
    }
    __syncthreads();

    const int k = tile * CD_THREADS + threadIdx.x;
    float local = 0.0f;
    if (k < K) {
        const float* __restrict__ a = adv + ((size_t)b * K + k) * 3;
        const float ax = a[0], ay = a[1], az = a[2];
        const unsigned long long axx = pack_dup(ax);
        const unsigned long long ayy = pack_dup(ay);
        const unsigned long long azz = pack_dup(az);

        const ulonglong2* __restrict__ pXY = (const ulonglong2*)sXY;
        const ulonglong2* __restrict__ pZW = (const ulonglong2*)sZW;

        float m[8];
#pragma unroll
        for (int i = 0; i < 8; ++i) m[i] = FLT_MAX;

        int p = 0;
        for (; p + 4 <= pairs; p += 4) {
#pragma unroll
            for (int u = 0; u < 4; ++u) {
                ulonglong2 A = pXY[p + u];   // A.x = x0x1, A.y = y0y1
                ulonglong2 Z = pZW[p + u];   // Z.x = z0z1, Z.y = w0w1
                unsigned long long t = fma2(azz, Z.x, Z.y);
                t = fma2(ayy, A.y, t);
                t = fma2(axx, A.x, t);
                float lo, hi;
                unpack2(t, lo, hi);
                m[2 * u]     = fminf(m[2 * u], lo);
                m[2 * u + 1] = fminf(m[2 * u + 1], hi);
            }
        }
        for (; p < pairs; ++p) {
            ulonglong2 A = pXY[p];
            ulonglong2 Z = pZW[p];
            unsigned long long t = fma2(azz, Z.x, Z.y);
            t = fma2(ayy, A.y, t);
            t = fma2(axx, A.x, t);
            float lo, hi;
            unpack2(t, lo, hi);
            m[0] = fminf(m[0], lo);
            m[1] = fminf(m[1], hi);
        }

        float mm = fminf(fminf(fminf(m[0], m[1]), fminf(m[2], m[3])),
                         fminf(fminf(m[4], m[5]), fminf(m[6], m[7])));
        local = mm + (ax * ax + ay * ay + az * az);
    }

    // Deterministic block reduction.
    __shared__ float red[CD_THREADS / 32];
    const int lane = threadIdx.x & 31;
    const int wid  = threadIdx.x >> 5;
#pragma unroll
    for (int off = 16; off > 0; off >>= 1)
        local += __shfl_down_sync(0xffffffffu, local, off);
    if (lane == 0) red[wid] = local;
    __syncthreads();
    if (threadIdx.x == 0) {
        float v = 0.0f;
#pragma unroll
        for (int i = 0; i < CD_THREADS / 32; ++i) v += red[i];
        g_cd_partial[blockIdx.x] = v * w[b];
    }

    // Last-block finalize (fixed summation order -> deterministic).
    __shared__ bool isLast;
    __threadfence();
    if (threadIdx.x == 0) {
        unsigned int c = atomicAdd(&g_cd_count, 1u);
        isLast = (c == (unsigned int)(nblocks - 1));
    }
    __syncthreads();
    if (isLast) {
        __threadfence();  // acquire: make all partials visible
        float s = 0.0f;
        for (int i = threadIdx.x; i < nblocks; i += CD_THREADS)
            s += g_cd_partial[i];
#pragma unroll
        for (int off = 16; off > 0; off >>= 1)
            s += __shfl_down_sync(0xffffffffu, s, off);
        if (lane == 0) red[wid] = s;
        __syncthreads();
        if (threadIdx.x == 0) {
            float v = 0.0f;
#pragma unroll
            for (int i = 0; i < CD_THREADS / 32; ++i) v += red[i];
            out[0] = v * scale;
            g_cd_count = 0u;  // reset for next graph replay
        }
    }
}

extern "C" void kernel_launch(void* const* d_in, const int* in_sizes, int n_in,
                              void* d_out, int out_size) {
    const float* adv = (const float*)d_in[0];   // [B, K, 3] float32
    const float* ori = (const float*)d_in[1];   // [B, K, 3] float32
    const float* w   = (const float*)d_in[2];   // [B]       float32
    float* out = (float*)d_out;                 // scalar float32

    const int B = in_sizes[2];
    const int K = in_sizes[0] / (3 * B);

    const int tilesPerBatch = (K + CD_THREADS - 1) / CD_THREADS;
    const int blocks = B * tilesPerBatch;

    const size_t smem = (size_t)(K / 2) * 2 * sizeof(float4);  // 64 KB @ K=4096
    cudaFuncSetAttribute(chamfer_fused_kernel,
                         cudaFuncAttributeMaxDynamicSharedMemorySize,
                         (int)smem);

    const float scale = 1.0f / ((float)B * (float)K);
    chamfer_fused_kernel<<<blocks, CD_THREADS, smem>>>(adv, ori, w, out, K,
                                                       tilesPerBatch, scale,
                                                       blocks);
}

// round 4
// speedup vs baseline: 1.4363x; 1.4363x over previous
#include <cuda_runtime.h>
#include <float.h>

// ChamferDist (adv->ori): loss = mean_b( w_b * mean_k( min_j ||adv[bk]-ori[bj]||^2 ) )
//
// min_j dist = a2 + min_j (b2_j - 2 a.b_j).
// Round-4 structure: 4 adv points per THREAD (ILP to hide LDS/FMA latency at
// 2 warps/SMSP), ori dimension split 4 ways across CTAs (j-split) so the grid
// still covers 128 SMs. Ori chunk (1024 pts) lives in smem as f32x2 pairs:
//   sXY[p] = (-2x0,-2x1,-2y0,-2y1), sZW[p] = (-2z0,-2z1,b2_0,b2_1)
// Inner iter (per ori pair): 2 LDS.128 + 12 FFMA2 + 8 FMNMX -> 8 pair-ops.
// Partial mins (incl. a2) -> scratch[point][4]; last CTA (atomic counter)
// min-combines + weighted deterministic sum -> scalar. Single launch.

#define CD_THREADS 256
#define CD_PTS 4
#define CD_JSPLIT 4
#define CD_CHUNK 1024               // = CD_THREADS * CD_PTS
#define CD_MAX_PTS 65536

__device__ float        g_cd_scratch[(size_t)CD_MAX_PTS * CD_JSPLIT];
__device__ unsigned int g_cd_count;

__device__ __forceinline__ unsigned long long pack_dup(float v) {
    unsigned long long r;
    asm("mov.b64 %0, {%1, %1};" : "=l"(r) : "f"(v));
    return r;
}
__device__ __forceinline__ unsigned long long fma2(unsigned long long a,
                                                   unsigned long long b,
                                                   unsigned long long c) {
    unsigned long long d;
    asm("fma.rn.f32x2 %0, %1, %2, %3;" : "=l"(d) : "l"(a), "l"(b), "l"(c));
    return d;
}
__device__ __forceinline__ void unpack2(unsigned long long v, float& lo, float& hi) {
    asm("mov.b64 {%0, %1}, %2;" : "=f"(lo), "=f"(hi) : "l"(v));
}

__global__ __launch_bounds__(CD_THREADS)
void chamfer_main_kernel(const float* __restrict__ adv,
                         const float* __restrict__ ori,
                         const float* __restrict__ w,
                         float* __restrict__ out,
                         int B, int K, int ktiles, float scale) {
    __shared__ float4 sXY[CD_CHUNK / 2];
    __shared__ float4 sZW[CD_CHUNK / 2];

    const int tid   = threadIdx.x;
    const int ktile = blockIdx.x % ktiles;
    const int rem   = blockIdx.x / ktiles;
    const int js    = rem % CD_JSPLIT;
    const int b     = rem / CD_JSPLIT;

    // ---- Fill smem with this CTA's ori chunk (pair layout, -2*coords, b2) ----
    const int j0g = js * CD_CHUNK;
    int cl = K - j0g;                         // points in this chunk
    if (cl > CD_CHUNK) cl = CD_CHUNK;
    if (cl < 0) cl = 0;
    const int pairsPad = (cl + 1) >> 1;       // odd tail: duplicate last point

    const float* __restrict__ orib = ori + (size_t)b * K * 3;
    for (int p = tid; p < pairsPad; p += CD_THREADS) {
        const int j0 = 2 * p;
        const int j1 = (2 * p + 1 < cl) ? (2 * p + 1) : (cl - 1);
        const float x0 = orib[(j0g + j0) * 3 + 0];
        const float y0 = orib[(j0g + j0) * 3 + 1];
        const float z0 = orib[(j0g + j0) * 3 + 2];
        const float x1 = orib[(j0g + j1) * 3 + 0];
        const float y1 = orib[(j0g + j1) * 3 + 1];
        const float z1 = orib[(j0g + j1) * 3 + 2];
        sXY[p] = make_float4(-2.0f * x0, -2.0f * x1, -2.0f * y0, -2.0f * y1);
        sZW[p] = make_float4(-2.0f * z0, -2.0f * z1,
                             x0 * x0 + y0 * y0 + z0 * z0,
                             x1 * x1 + y1 * y1 + z1 * z1);
    }
    __syncthreads();

    // ---- 4 adv points per thread ----
    int   kk[CD_PTS];
    float ax[CD_PTS], ay[CD_PTS], az[CD_PTS], a2[CD_PTS];
    unsigned long long axx[CD_PTS], ayy[CD_PTS], azz[CD_PTS];
#pragma unroll
    for (int u = 0; u < CD_PTS; ++u) {
        const int k = ktile * CD_CHUNK + tid + u * CD_THREADS;
        kk[u] = k;
        float x = 0.f, y = 0.f, z = 0.f;
        if (k < K) {
            const float* __restrict__ a = adv + ((size_t)b * K + k) * 3;
            x = a[0]; y = a[1]; z = a[2];
        }
        ax[u] = x; ay[u] = y; az[u] = z;
        a2[u] = x * x + y * y + z * z;
        axx[u] = pack_dup(x); ayy[u] = pack_dup(y); azz[u] = pack_dup(z);
    }

    float mlo[CD_PTS], mhi[CD_PTS];
#pragma unroll
    for (int u = 0; u < CD_PTS; ++u) { mlo[u] = FLT_MAX; mhi[u] = FLT_MAX; }

    const ulonglong2* __restrict__ pXY = (const ulonglong2*)sXY;
    const ulonglong2* __restrict__ pZW = (const ulonglong2*)sZW;

#pragma unroll 2
    for (int p = 0; p < pairsPad; ++p) {
        const ulonglong2 A = pXY[p];   // A.x = (x0,x1)  A.y = (y0,y1)
        const ulonglong2 Z = pZW[p];   // Z.x = (z0,z1)  Z.y = (b2_0,b2_1)
#pragma unroll
        for (int u = 0; u < CD_PTS; ++u) {
            unsigned long long t = fma2(azz[u], Z.x, Z.y);
            t = fma2(ayy[u], A.y, t);
            t = fma2(axx[u], A.x, t);
            float lo, hi;
            unpack2(t, lo, hi);
            mlo[u] = fminf(mlo[u], lo);
            mhi[u] = fminf(mhi[u], hi);
        }
    }

    // ---- Write partial mins (a2 folded in; min over splits later) ----
#pragma unroll
    for (int u = 0; u < CD_PTS; ++u) {
        if (kk[u] < K) {
            const float m = fminf(mlo[u], mhi[u]) + a2[u];
            g_cd_scratch[((size_t)b * K + kk[u]) * CD_JSPLIT + js] = m;
        }
    }

    // ---- Last-CTA combine (fixed-order, deterministic) ----
    __shared__ bool isLast;
    __threadfence();
    if (tid == 0) {
        const unsigned int c = atomicAdd(&g_cd_count, 1u);
        isLast = (c == gridDim.x - 1);
    }
    __syncthreads();
    if (!isLast) return;

    __threadfence();
    float acc = 0.0f;
    for (int bb = 0; bb < B; ++bb) {
        const float4* __restrict__ sc =
            (const float4*)&g_cd_scratch[(size_t)bb * K * CD_JSPLIT];
        float s = 0.0f;
        for (int i = tid; i < K; i += CD_THREADS) {
            const float4 v = sc[i];
            s += fminf(fminf(v.x, v.y), fminf(v.z, v.w));
        }
        acc += s * w[bb];
    }

    __shared__ float red[CD_THREADS / 32];
    const int lane = tid & 31;
    const int wid  = tid >> 5;
#pragma unroll
    for (int off = 16; off > 0; off >>= 1)
        acc += __shfl_down_sync(0xffffffffu, acc, off);
    if (lane == 0) red[wid] = acc;
    __syncthreads();
    if (tid == 0) {
        float v = 0.0f;
#pragma unroll
        for (int i = 0; i < CD_THREADS / 32; ++i) v += red[i];
        out[0] = v * scale;
        g_cd_count = 0u;   // reset for graph replay
    }
}

extern "C" void kernel_launch(void* const* d_in, const int* in_sizes, int n_in,
                              void* d_out, int out_size) {
    const float* adv = (const float*)d_in[0];   // [B, K, 3] float32
    const float* ori = (const float*)d_in[1];   // [B, K, 3] float32
    const float* w   = (const float*)d_in[2];   // [B]       float32
    float* out = (float*)d_out;                 // scalar float32

    const int B = in_sizes[2];
    const int K = in_sizes[0] / (3 * B);

    const int ktiles = (K + CD_CHUNK - 1) / CD_CHUNK;
    const int blocks = B * CD_JSPLIT * ktiles;   // 8*4*4 = 128 @ B=8,K=4096

    const float scale = 1.0f / ((float)B * (float)K);
    chamfer_main_kernel<<<blocks, CD_THREADS>>>(adv, ori, w, out,
                                                B, K, ktiles, scale);
}

// round 5
// speedup vs baseline: 1.9052x; 1.3265x over previous
#include <cuda_runtime.h>
#include <float.h>

// ChamferDist (adv->ori): loss = mean_b( w_b * mean_k( min_j ||adv[bk]-ori[bj]||^2 ) )
//
// min_j dist = a2_k + min_j (b2_j - 2 a_k.b_j).
// R5 structure:
//   grid = B x JSPLIT(8) x KTILES, 256 threads, 4 adv pts/thread, 8KB smem
//   -> 2 CTAs/SM (16 warps/SM) for latency hiding.
//   Ori j-chunk (512 pts) in smem as f32x2 pairs:
//     sXY[p]=(-2x0,-2x1,-2y0,-2y1), sZW[p]=(-2z0,-2z1,b2_0,b2_1)
//   Inner iter: 2 LDS.128 + 12 FFMA2 + 8 FMNMX for 8 pair-ops.
//   Combine: scratch[point][8] partial mins; per-(b,ktile) counter -> group's
//   last CTA min-combines + weighted sum; global counter -> last group writes
//   the scalar. Single launch, deterministic (fixed-order reductions).

#define CD_THREADS 256
#define CD_PTS     4
#define CD_JS      8
#define CD_KCHUNK  1024          // CD_THREADS * CD_PTS
#define CD_JCHUNK  512
#define CD_PAIRS   256           // CD_JCHUNK / 2
#define CD_MAX_SCRATCH (1 << 20) // floats
#define CD_MAX_GROUPS  1024

__device__ float        g_cd_scratch[CD_MAX_SCRATCH];
__device__ float        g_cd_group[CD_MAX_GROUPS];
__device__ unsigned int g_cd_tile_count[CD_MAX_GROUPS];
__device__ unsigned int g_cd_final_count;

__device__ __forceinline__ unsigned long long pack_dup(float v) {
    unsigned long long r;
    asm("mov.b64 %0, {%1, %1};" : "=l"(r) : "f"(v));
    return r;
}
__device__ __forceinline__ unsigned long long fma2(unsigned long long a,
                                                   unsigned long long b,
                                                   unsigned long long c) {
    unsigned long long d;
    asm("fma.rn.f32x2 %0, %1, %2, %3;" : "=l"(d) : "l"(a), "l"(b), "l"(c));
    return d;
}

__global__ __launch_bounds__(CD_THREADS, 2)
void chamfer_main_kernel(const float* __restrict__ adv,
                         const float* __restrict__ ori,
                         const float* __restrict__ w,
                         float* __restrict__ out,
                         int B, int K, int ktiles, float scale) {
    __shared__ float4 sXY[CD_PAIRS];
    __shared__ float4 sZW[CD_PAIRS];
    __shared__ float  red[CD_THREADS / 32];
    __shared__ bool   sFlag;

    const int tid = threadIdx.x;
    const int kt  = blockIdx.x % ktiles;
    const int rem = blockIdx.x / ktiles;
    const int js  = rem % CD_JS;
    const int b   = rem / CD_JS;
    const int ngroups = B * ktiles;
    const int gid = b * ktiles + kt;

    // ---- Fill smem with this CTA's ori j-chunk ----
    const int j0g = js * CD_JCHUNK;
    int cl = K - j0g;
    if (cl > CD_JCHUNK) cl = CD_JCHUNK;
    if (cl < 0) cl = 0;
    const int pairsPad = (cl + 1) >> 1;

    const float* __restrict__ orib = ori + (size_t)b * K * 3;
    if (tid < pairsPad) {
        const int p  = tid;
        const int j0 = 2 * p;
        const int j1 = (2 * p + 1 < cl) ? (2 * p + 1) : (cl - 1);
        const float x0 = orib[(j0g + j0) * 3 + 0];
        const float y0 = orib[(j0g + j0) * 3 + 1];
        const float z0 = orib[(j0g + j0) * 3 + 2];
        const float x1 = orib[(j0g + j1) * 3 + 0];
        const float y1 = orib[(j0g + j1) * 3 + 1];
        const float z1 = orib[(j0g + j1) * 3 + 2];
        sXY[p] = make_float4(-2.0f * x0, -2.0f * x1, -2.0f * y0, -2.0f * y1);
        sZW[p] = make_float4(-2.0f * z0, -2.0f * z1,
                             x0 * x0 + y0 * y0 + z0 * z0,
                             x1 * x1 + y1 * y1 + z1 * z1);
    }
    __syncthreads();

    // ---- 4 adv points per thread ----
    int   kk[CD_PTS];
    float a2[CD_PTS];
    unsigned long long axx[CD_PTS], ayy[CD_PTS], azz[CD_PTS];
#pragma unroll
    for (int u = 0; u < CD_PTS; ++u) {
        const int k = kt * CD_KCHUNK + tid + u * CD_THREADS;
        kk[u] = k;
        float x = 0.f, y = 0.f, z = 0.f;
        if (k < K) {
            const float* __restrict__ a = adv + ((size_t)b * K + k) * 3;
            x = a[0]; y = a[1]; z = a[2];
        }
        a2[u]  = x * x + y * y + z * z;
        axx[u] = pack_dup(x); ayy[u] = pack_dup(y); azz[u] = pack_dup(z);
    }

    float mlo[CD_PTS], mhi[CD_PTS];
#pragma unroll
    for (int u = 0; u < CD_PTS; ++u) { mlo[u] = FLT_MAX; mhi[u] = FLT_MAX; }

    const ulonglong2* __restrict__ pXY = (const ulonglong2*)sXY;
    const ulonglong2* __restrict__ pZW = (const ulonglong2*)sZW;

#pragma unroll 4
    for (int p = 0; p < pairsPad; ++p) {
        const ulonglong2 A = pXY[p];   // (x0,x1) , (y0,y1)
        const ulonglong2 Z = pZW[p];   // (z0,z1) , (b2_0,b2_1)
#pragma unroll
        for (int u = 0; u < CD_PTS; ++u) {
            union { unsigned long long u64; float2 f2; } t;
            t.u64 = fma2(azz[u], Z.x, Z.y);
            t.u64 = fma2(ayy[u], A.y, t.u64);
            t.u64 = fma2(axx[u], A.x, t.u64);
            mlo[u] = fminf(mlo[u], t.f2.x);
            mhi[u] = fminf(mhi[u], t.f2.y);
        }
    }

    // ---- Write partial mins (a2 folded in) ----
#pragma unroll
    for (int u = 0; u < CD_PTS; ++u) {
        if (kk[u] < K) {
            g_cd_scratch[((size_t)b * K + kk[u]) * CD_JS + js] =
                fminf(mlo[u], mhi[u]) + a2[u];
        }
    }

    // ---- Per-(b,ktile) group combine by the group's last CTA ----
    __threadfence();
    if (tid == 0) {
        const unsigned int c = atomicAdd(&g_cd_tile_count[gid], 1u);
        sFlag = (c == (unsigned int)(CD_JS - 1));
    }
    __syncthreads();
    if (!sFlag) return;
    __threadfence();

    {
        const int kbase = kt * CD_KCHUNK;
        int npts = K - kbase;
        if (npts > CD_KCHUNK) npts = CD_KCHUNK;
        const float* __restrict__ base =
            g_cd_scratch + ((size_t)b * K + kbase) * CD_JS;
        float s = 0.0f;
        for (int i = tid; i < npts; i += CD_THREADS) {
            const float4* __restrict__ pp = (const float4*)(base + (size_t)i * CD_JS);
            const float4 v1 = pp[0];
            const float4 v2 = pp[1];
            s += fminf(fminf(fminf(v1.x, v1.y), fminf(v1.z, v1.w)),
                       fminf(fminf(v2.x, v2.y), fminf(v2.z, v2.w)));
        }
        const int lane = tid & 31, wid = tid >> 5;
#pragma unroll
        for (int off = 16; off > 0; off >>= 1)
            s += __shfl_down_sync(0xffffffffu, s, off);
        if (lane == 0) red[wid] = s;
        __syncthreads();
        if (tid == 0) {
            float v = 0.0f;
#pragma unroll
            for (int i = 0; i < CD_THREADS / 32; ++i) v += red[i];
            g_cd_group[gid] = v * w[b];
            g_cd_tile_count[gid] = 0u;   // reset for graph replay
            __threadfence();
            const unsigned int c = atomicAdd(&g_cd_final_count, 1u);
            sFlag = (c == (unsigned int)(ngroups - 1));
        }
        __syncthreads();
        if (!sFlag) return;

        // ---- Final: sum the (<=64) group sums, fixed order ----
        if (tid == 0) {
            __threadfence();
            float v = 0.0f;
#pragma unroll 8
            for (int i = 0; i < ngroups; ++i) v += g_cd_group[i];
            out[0] = v * scale;
            g_cd_final_count = 0u;       // reset for graph replay
        }
    }
}

extern "C" void kernel_launch(void* const* d_in, const int* in_sizes, int n_in,
                              void* d_out, int out_size) {
    const float* adv = (const float*)d_in[0];   // [B, K, 3] float32
    const float* ori = (const float*)d_in[1];   // [B, K, 3] float32
    const float* w   = (const float*)d_in[2];   // [B]       float32
    float* out = (float*)d_out;                 // scalar float32

    const int B = in_sizes[2];
    const int K = in_sizes[0] / (3 * B);

    const int ktiles = (K + CD_KCHUNK - 1) / CD_KCHUNK;
    const int blocks = B * CD_JS * ktiles;      // 8*8*4 = 256 @ B=8,K=4096

    const float scale = 1.0f / ((float)B * (float)K);
    chamfer_main_kernel<<<blocks, CD_THREADS>>>(adv, ori, w, out,
                                                B, K, ktiles, scale);
}